// round 4
// baseline (speedup 1.0000x reference)
#include <cuda_runtime.h>
#include <cuda_bf16.h>
#include <math_constants.h>

#define NMAX 30000
#define EMAX 480000
#define GNUM 64
#define HF 64
#define HEADS 8
#define MLPD 256

// ------------------------- device scratch -------------------------
__device__ float g_h   [NMAX * HF];
__device__ float g_agg [NMAX * HEADS * HF];   // layer1 per-head agg; layer2 reuses first 64 cols
__device__ float g_rst [NMAX * HEADS * HF];   // layer1 per-head LN'ed output
__device__ float g_el  [NMAX * HEADS];
__device__ float g_er  [NMAX * HEADS];
__device__ float g_h2  [NMAX * HF];
__device__ float g_w   [EMAX * HEADS];
__device__ int   g_indeg [NMAX];
__device__ int   g_cursor[NMAX];
__device__ int   g_rowptr[NMAX + 1];
__device__ int   g_srcs  [EMAX];
__device__ int   g_pos   [EMAX];
__device__ float g_hg   [GNUM * HF];
__device__ float g_pool1[GNUM * HF];
__device__ float g_pool2[GNUM * HF];
__device__ float g_wl1[HEADS * HF], g_wr1[HEADS * HF];
__device__ float g_wl2[HF],        g_wr2[HF];

// ------------------------- f32x2 helpers -------------------------
typedef unsigned long long u64;

__device__ __forceinline__ u64 dup2(float a) {
    u64 r;
    asm("mov.b64 %0, {%1, %1};" : "=l"(r) : "r"(__float_as_uint(a)));
    return r;
}
__device__ __forceinline__ float2 unpack2(u64 v) {
    unsigned lo, hi;
    asm("mov.b64 {%0, %1}, %2;" : "=r"(lo), "=r"(hi) : "l"(v));
    return make_float2(__uint_as_float(lo), __uint_as_float(hi));
}
#define FMA2(d, a, b) asm("fma.rn.f32x2 %0, %1, %2, %0;" : "+l"(d) : "l"(a), "l"(b))

// ------------------------- GEMM core (M-tile 128, N 64, K-chunk 32) -------------------------
// 128 threads: tx = t&7 (8 cols of 8), ty = t>>3 (16 rows of 8). acc packed along N.
__device__ __forceinline__ void mm_loadA(float (*As)[33], const float* __restrict__ A,
                                         int lda, int m0, int koff, int M, int t) {
#pragma unroll
    for (int j = 0; j < 8; j++) {
        int idx = t + 128 * j;
        int r = idx >> 3, c4 = idx & 7;
        int row = m0 + r;
        float4 v = (row < M) ? *(const float4*)&A[(size_t)row * lda + koff + c4 * 4]
                             : make_float4(0.f, 0.f, 0.f, 0.f);
        As[r][c4 * 4 + 0] = v.x; As[r][c4 * 4 + 1] = v.y;
        As[r][c4 * 4 + 2] = v.z; As[r][c4 * 4 + 3] = v.w;
    }
}
__device__ __forceinline__ void mm_loadW(float (*Ws)[64], const float* __restrict__ W,
                                         int ldw, int k0, int n0, int t) {
#pragma unroll
    for (int j = 0; j < 4; j++) {
        int idx = t + 128 * j;
        int k = idx >> 4, c4 = idx & 15;
        *(float4*)&Ws[k][c4 * 4] = *(const float4*)&W[(size_t)(k0 + k) * ldw + n0 + c4 * 4];
    }
}
__device__ __forceinline__ void mm_chunk(const float (*As)[33], const float (*Ws)[64],
                                         u64 acc[8][4], int tx, int ty) {
#pragma unroll
    for (int k = 0; k < 32; k++) {
        const u64* wp = (const u64*)&Ws[k][tx * 8];
        u64 b0 = wp[0], b1 = wp[1], b2 = wp[2], b3 = wp[3];
#pragma unroll
        for (int i = 0; i < 8; i++) {
            u64 a2 = dup2(As[ty * 8 + i][k]);
            FMA2(acc[i][0], a2, b0);
            FMA2(acc[i][1], a2, b1);
            FMA2(acc[i][2], a2, b2);
            FMA2(acc[i][3], a2, b3);
        }
    }
}

// ------------------------- proj GEMM: h = X@projW + b; hg += pool(h) -------------------------
__global__ __launch_bounds__(128) void k_gemm_proj(
    const float* __restrict__ X, const float* __restrict__ W, const float* __restrict__ bias,
    const int* __restrict__ gid, float* __restrict__ h, float* __restrict__ hg, int M) {
    __shared__ float As[128][33];
    __shared__ float Ws[32][64];
    int t = threadIdx.x, tx = t & 7, ty = t >> 3;
    int m0 = blockIdx.x * 128;
    u64 acc[8][4] = {};
#pragma unroll
    for (int c = 0; c < 2; c++) {
        mm_loadA(As, X, 64, m0, c * 32, M, t);
        mm_loadW(Ws, W, 64, c * 32, 0, t);
        __syncthreads();
        mm_chunk(As, Ws, acc, tx, ty);
        __syncthreads();
    }
    float bv[8];
#pragma unroll
    for (int j = 0; j < 8; j++) bv[j] = bias[tx * 8 + j];
#pragma unroll
    for (int i = 0; i < 8; i++) {
        int row = m0 + ty * 8 + i;
        if (row >= M) break;
        float c[8];
#pragma unroll
        for (int jj = 0; jj < 4; jj++) {
            float2 p = unpack2(acc[i][jj]);
            c[jj * 2] = p.x + bv[jj * 2];
            c[jj * 2 + 1] = p.y + bv[jj * 2 + 1];
        }
        *(float4*)&h[(size_t)row * 64 + tx * 8]     = make_float4(c[0], c[1], c[2], c[3]);
        *(float4*)&h[(size_t)row * 64 + tx * 8 + 4] = make_float4(c[4], c[5], c[6], c[7]);
        int g = gid[row];
#pragma unroll
        for (int j = 0; j < 8; j++) atomicAdd(&hg[g * 64 + tx * 8 + j], c[j]);
    }
}

// -------- cat1 GEMM: per-head [agg_h | h] @ [fcW1_h; resW1_h] + bias -> ELU -> LN -> rst ------
__global__ __launch_bounds__(128) void k_gemm_cat1(
    const float* __restrict__ agg, const float* __restrict__ hfeat,
    const float* __restrict__ fcW1, const float* __restrict__ resW1,
    const float* __restrict__ bias, float* __restrict__ rst, int M) {
    __shared__ float As[128][33];
    __shared__ float Ws[32][64];
    int t = threadIdx.x, tx = t & 7, ty = t >> 3;
    int m0 = blockIdx.x * 128;
    int hb = blockIdx.y;
    u64 acc[8][4] = {};
#pragma unroll
    for (int c = 0; c < 4; c++) {
        const float* Ap = (c < 2) ? agg : hfeat;
        int lda = (c < 2) ? 512 : 64;
        int aoff = ((c < 2) ? hb * 64 : 0) + (c & 1) * 32;
        const float* Wp = (c < 2) ? fcW1 : resW1;
        int k0 = (c & 1) * 32;
        mm_loadA(As, Ap, lda, m0, aoff, M, t);
        mm_loadW(Ws, Wp, 512, k0, hb * 64, t);
        __syncthreads();
        mm_chunk(As, Ws, acc, tx, ty);
        __syncthreads();
    }
    float bv[8];
#pragma unroll
    for (int j = 0; j < 8; j++) bv[j] = bias[hb * 64 + tx * 8 + j];
#pragma unroll
    for (int i = 0; i < 8; i++) {
        int row = m0 + ty * 8 + i;
        float c[8];
        float s = 0.f, q = 0.f;
#pragma unroll
        for (int jj = 0; jj < 4; jj++) {
            float2 p = unpack2(acc[i][jj]);
            float v0 = p.x + bv[jj * 2];
            float v1 = p.y + bv[jj * 2 + 1];
            v0 = v0 > 0.f ? v0 : expm1f(v0);
            v1 = v1 > 0.f ? v1 : expm1f(v1);
            c[jj * 2] = v0; c[jj * 2 + 1] = v1;
            s += v0 + v1; q += v0 * v0 + v1 * v1;
        }
#pragma unroll
        for (int o = 1; o < 8; o <<= 1) {
            s += __shfl_xor_sync(~0u, s, o);
            q += __shfl_xor_sync(~0u, q, o);
        }
        float mu = s * (1.f / 64.f);
        float sc = rsqrtf(q * (1.f / 64.f) - mu * mu + 1e-5f);
        if (row < M) {
            float4 o0 = make_float4((c[0] - mu) * sc, (c[1] - mu) * sc,
                                    (c[2] - mu) * sc, (c[3] - mu) * sc);
            float4 o1 = make_float4((c[4] - mu) * sc, (c[5] - mu) * sc,
                                    (c[6] - mu) * sc, (c[7] - mu) * sc);
            *(float4*)&rst[(size_t)row * 512 + hb * 64 + tx * 8]     = o0;
            *(float4*)&rst[(size_t)row * 512 + hb * 64 + tx * 8 + 4] = o1;
        }
    }
}

// -------- layer2 GEMM: agg2@fcW2 + h2 + b2 -> ELU -> LN -> atomic pool2 (no h3) --------
__global__ __launch_bounds__(128) void k_gemm_epi2(
    const float* __restrict__ agg2, const float* __restrict__ fcW2,
    const float* __restrict__ h2, const float* __restrict__ bias,
    const int* __restrict__ gid, float* __restrict__ pool2, int M) {
    __shared__ float As[128][33];
    __shared__ float Ws[32][64];
    int t = threadIdx.x, tx = t & 7, ty = t >> 3;
    int m0 = blockIdx.x * 128;
    u64 acc[8][4] = {};
#pragma unroll
    for (int c = 0; c < 2; c++) {
        mm_loadA(As, agg2, 64, m0, c * 32, M, t);
        mm_loadW(Ws, fcW2, 64, c * 32, 0, t);
        __syncthreads();
        mm_chunk(As, Ws, acc, tx, ty);
        __syncthreads();
    }
    float bv[8];
#pragma unroll
    for (int j = 0; j < 8; j++) bv[j] = bias[tx * 8 + j];
#pragma unroll
    for (int i = 0; i < 8; i++) {
        int row = m0 + ty * 8 + i;
        bool valid = row < M;
        float4 h0 = valid ? *(const float4*)&h2[(size_t)row * 64 + tx * 8]
                          : make_float4(0.f, 0.f, 0.f, 0.f);
        float4 h1 = valid ? *(const float4*)&h2[(size_t)row * 64 + tx * 8 + 4]
                          : make_float4(0.f, 0.f, 0.f, 0.f);
        float hres[8] = {h0.x, h0.y, h0.z, h0.w, h1.x, h1.y, h1.z, h1.w};
        float c[8];
        float s = 0.f, q = 0.f;
#pragma unroll
        for (int jj = 0; jj < 4; jj++) {
            float2 p = unpack2(acc[i][jj]);
            float v0 = p.x + hres[jj * 2] + bv[jj * 2];
            float v1 = p.y + hres[jj * 2 + 1] + bv[jj * 2 + 1];
            v0 = v0 > 0.f ? v0 : expm1f(v0);
            v1 = v1 > 0.f ? v1 : expm1f(v1);
            c[jj * 2] = v0; c[jj * 2 + 1] = v1;
            s += v0 + v1; q += v0 * v0 + v1 * v1;
        }
#pragma unroll
        for (int o = 1; o < 8; o <<= 1) {
            s += __shfl_xor_sync(~0u, s, o);
            q += __shfl_xor_sync(~0u, q, o);
        }
        float mu = s * (1.f / 64.f);
        float sc = rsqrtf(q * (1.f / 64.f) - mu * mu + 1e-5f);
        if (valid) {
            int g = gid[row];
#pragma unroll
            for (int j = 0; j < 8; j++)
                atomicAdd(&pool2[g * 64 + tx * 8 + j], (c[j] - mu) * sc);
        }
    }
}

// ------------------------- init / CSR -------------------------
__global__ void k_init(int* indeg, int* cursor, float* hg, float* pool1, float* pool2, int N) {
    int i = blockIdx.x * blockDim.x + threadIdx.x;
    if (i < N) { indeg[i] = 0; cursor[i] = 0; }
    if (i < GNUM * HF) { hg[i] = 0.f; pool1[i] = 0.f; pool2[i] = 0.f; }
}

__global__ void k_hist(const int* __restrict__ dst, int* __restrict__ indeg, int E) {
    int e = blockIdx.x * blockDim.x + threadIdx.x;
    if (e < E) atomicAdd(&indeg[dst[e]], 1);
}

__global__ void k_scan(const int* __restrict__ indeg, int* __restrict__ rowptr, int n) {
    __shared__ int warpsum[32];
    __shared__ int s_total;
    int t = threadIdx.x, lane = t & 31, w = t >> 5;
    int carry = 0;
    for (int base = 0; base < n; base += 1024) {
        int idx = base + t;
        int v = (idx < n) ? indeg[idx] : 0;
        int x = v;
#pragma unroll
        for (int o = 1; o < 32; o <<= 1) {
            int y = __shfl_up_sync(~0u, x, o);
            if (lane >= o) x += y;
        }
        if (lane == 31) warpsum[w] = x;
        __syncthreads();
        if (w == 0) {
            int y = warpsum[lane];
#pragma unroll
            for (int o = 1; o < 32; o <<= 1) {
                int z = __shfl_up_sync(~0u, y, o);
                if (lane >= o) y += z;
            }
            warpsum[lane] = y;
            if (lane == 31) s_total = y;
        }
        __syncthreads();
        int off = carry + (w ? warpsum[w - 1] : 0);
        if (idx < n) rowptr[idx] = off + x - v;
        carry += s_total;
        __syncthreads();
    }
    if (t == 0) rowptr[n] = carry;
}

// ------------------------- attention prep / coefficients -------------------------
__global__ void k_prep_all(const float* __restrict__ fcW1, const float* __restrict__ al1,
                           const float* __restrict__ ar1, const float* __restrict__ fcW2,
                           const float* __restrict__ al2, const float* __restrict__ ar2,
                           float* __restrict__ wl1, float* __restrict__ wr1,
                           float* __restrict__ wl2, float* __restrict__ wr2) {
    int b = blockIdx.x, t = threadIdx.x;
    if (b < 2) {
        int idx = b * 256 + t;
        int h = idx >> 6, i = idx & 63;
        float sl = 0.f, sr = 0.f;
#pragma unroll 16
        for (int d = 0; d < 64; d++) {
            float v = fcW1[i * 512 + h * 64 + d];
            sl += v * al1[h * 64 + d];
            sr += v * ar1[h * 64 + d];
        }
        wl1[idx] = sl; wr1[idx] = sr;
    } else if (t < 64) {
        float sl = 0.f, sr = 0.f;
#pragma unroll 16
        for (int d = 0; d < 64; d++) {
            float v = fcW2[t * 64 + d];
            sl += v * al2[d];
            sr += v * ar2[d];
        }
        wl2[t] = sl; wr2[t] = sr;
    }
}

template <int H>
__global__ void k_attn(const float* __restrict__ hfeat, const float* __restrict__ wl,
                       const float* __restrict__ wr, float* __restrict__ el,
                       float* __restrict__ er, int N) {
    __shared__ float swl[H * 64], swr[H * 64];
    int t = threadIdx.x;
    for (int i = t; i < H * 64; i += blockDim.x) { swl[i] = wl[i]; swr[i] = wr[i]; }
    __syncthreads();
    int lane = t & 31;
    int node = blockIdx.x * (blockDim.x >> 5) + (t >> 5);
    if (node >= N) return;
    float2 f = *(const float2*)&hfeat[(size_t)node * 64 + lane * 2];
#pragma unroll
    for (int h = 0; h < H; h++) {
        float sl = f.x * swl[h * 64 + lane * 2] + f.y * swl[h * 64 + lane * 2 + 1];
        float sr = f.x * swr[h * 64 + lane * 2] + f.y * swr[h * 64 + lane * 2 + 1];
#pragma unroll
        for (int o = 16; o; o >>= 1) {
            sl += __shfl_xor_sync(~0u, sl, o);
            sr += __shfl_xor_sync(~0u, sr, o);
        }
        if (lane == 0) { el[node * H + h] = sl; er[node * H + h] = sr; }
    }
}

// ------------------------- edge kernels -------------------------
__global__ void k_edge1_h8(const int* __restrict__ src, const int* __restrict__ dst,
                           const float* __restrict__ el, const float* __restrict__ er,
                           const int* __restrict__ rowptr, int* __restrict__ cursor,
                           int* __restrict__ srcs, int* __restrict__ pos_out,
                           float* __restrict__ w, int E) {
    int e = blockIdx.x * blockDim.x + threadIdx.x;
    if (e >= E) return;
    int s = src[e], d = dst[e];
    int pos = rowptr[d] + atomicAdd(&cursor[d], 1);
    pos_out[e] = pos;
    srcs[pos] = s;
    float4 el0 = *(const float4*)&el[s * 8];
    float4 el1 = *(const float4*)&el[s * 8 + 4];
    float4 er0 = *(const float4*)&er[d * 8];
    float4 er1 = *(const float4*)&er[d * 8 + 4];
    float x[8] = {el0.x + er0.x, el0.y + er0.y, el0.z + er0.z, el0.w + er0.w,
                  el1.x + er1.x, el1.y + er1.y, el1.z + er1.z, el1.w + er1.w};
    float4 w0, w1;
#pragma unroll
    for (int h = 0; h < 8; h++) {
        float v = x[h] > 0.f ? x[h] : 0.2f * x[h];
        float ex = __expf(v);
        if (h < 4) ((float*)&w0)[h] = ex; else ((float*)&w1)[h - 4] = ex;
    }
    *(float4*)&w[(size_t)pos * 8] = w0;
    *(float4*)&w[(size_t)pos * 8 + 4] = w1;
}

__global__ void k_edge2_h1(const int* __restrict__ src, const int* __restrict__ dst,
                           const float* __restrict__ el, const float* __restrict__ er,
                           const int* __restrict__ pos_in, float* __restrict__ w, int E) {
    int e = blockIdx.x * blockDim.x + threadIdx.x;
    if (e >= E) return;
    float x = el[src[e]] + er[dst[e]];
    x = x > 0.f ? x : 0.2f * x;
    w[pos_in[e]] = __expf(x);
}

// ------------------------- aggregation -------------------------
__global__ void k_agg_h8(const int* __restrict__ srcs, const float* __restrict__ hfeat,
                         const float* __restrict__ w, const int* __restrict__ rowptr,
                         float* __restrict__ agg, int N) {
    int node = blockIdx.x * 8 + (threadIdx.x >> 5);
    int lane = threadIdx.x & 31;
    if (node >= N) return;
    int rs = rowptr[node], deg = rowptr[node + 1] - rs;
    float ax[8], ay[8], den[8];
#pragma unroll
    for (int h = 0; h < 8; h++) { ax[h] = 0.f; ay[h] = 0.f; den[h] = 0.f; }
    for (int k = 0; k < deg; k++) {
        int s = srcs[rs + k];
        float2 hv = *(const float2*)&hfeat[(size_t)s * 64 + lane * 2];
        float4 w0 = *(const float4*)&w[(size_t)(rs + k) * 8];
        float4 w1 = *(const float4*)&w[(size_t)(rs + k) * 8 + 4];
        const float* ww = (const float*)&w0;
#pragma unroll
        for (int h = 0; h < 4; h++) {
            ax[h] += ww[h] * hv.x; ay[h] += ww[h] * hv.y; den[h] += ww[h];
        }
        const float* ww2 = (const float*)&w1;
#pragma unroll
        for (int h = 0; h < 4; h++) {
            ax[4 + h] += ww2[h] * hv.x; ay[4 + h] += ww2[h] * hv.y; den[4 + h] += ww2[h];
        }
    }
#pragma unroll
    for (int h = 0; h < 8; h++) {
        float inv = (deg > 0) ? 1.f / den[h] : 0.f;
        *(float2*)&agg[(size_t)node * 512 + h * 64 + lane * 2] =
            make_float2(ax[h] * inv, ay[h] * inv);
    }
}

__global__ void k_agg_h1(const int* __restrict__ srcs, const float* __restrict__ hfeat,
                         const float* __restrict__ w, const int* __restrict__ rowptr,
                         float* __restrict__ agg, int N) {
    int node = blockIdx.x * 8 + (threadIdx.x >> 5);
    int lane = threadIdx.x & 31;
    if (node >= N) return;
    int rs = rowptr[node], deg = rowptr[node + 1] - rs;
    float ax = 0.f, ay = 0.f, den = 0.f;
    for (int k = 0; k < deg; k++) {
        int s = srcs[rs + k];
        float ww = w[rs + k];
        float2 hv = *(const float2*)&hfeat[(size_t)s * 64 + lane * 2];
        ax += ww * hv.x; ay += ww * hv.y; den += ww;
    }
    float inv = (deg > 0) ? 1.f / den : 0.f;
    *(float2*)&agg[(size_t)node * 64 + lane * 2] = make_float2(ax * inv, ay * inv);
}

// ------------------------- head mean + pool1 -------------------------
__global__ void k_mean8(const float* __restrict__ rst, const int* __restrict__ gid,
                        float* __restrict__ h2, float* __restrict__ pool1, int N) {
    int i = blockIdx.x * blockDim.x + threadIdx.x;
    if (i >= N * 64) return;
    int n = i >> 6, c = i & 63;
    float s = 0.f;
#pragma unroll
    for (int h = 0; h < 8; h++) s += rst[(size_t)n * 512 + h * 64 + c];
    s *= 0.125f;
    h2[i] = s;
    atomicAdd(&pool1[gid[n] * 64 + c], s);
}

// ------------------------- graph head -------------------------
__global__ void k_hg_update(const float* __restrict__ p, const float* __restrict__ W,
                            const float* __restrict__ b, float* __restrict__ hg) {
    int g = blockIdx.x, f = threadIdx.x;
    __shared__ float pr[64];
    pr[f] = p[g * 64 + f];
    __syncthreads();
    float s = b[f];
#pragma unroll 16
    for (int k = 0; k < 64; k++) s += pr[k] * W[k * 64 + f];
    s = s > 0.f ? s : 0.01f * s;
    hg[g * 64 + f] += s;
}

__global__ void k_mlp(const float* __restrict__ hg, const float* __restrict__ mW0,
                      const float* __restrict__ mb0, const float* __restrict__ mW1,
                      const float* __restrict__ mb1, const float* __restrict__ mW2,
                      const float* __restrict__ mb2, float* __restrict__ out) {
    int g = blockIdx.x;
    int t = threadIdx.x;
    __shared__ float x0[64], x1[256];
    if (t < 64) x0[t] = hg[g * 64 + t];
    __syncthreads();
    float s = mb0[t];
#pragma unroll 16
    for (int k = 0; k < 64; k++) s += x0[k] * mW0[k * 256 + t];
    x1[t] = fmaxf(s, 0.f);
    __syncthreads();
    s = mb1[t];
#pragma unroll 16
    for (int k = 0; k < 256; k++) s += x1[k] * mW1[k * 256 + t];
    float y = fmaxf(s, 0.f);
    __syncthreads();
    x1[t] = y;
    __syncthreads();
    s = mb2[t];
#pragma unroll 16
    for (int k = 0; k < 256; k++) s += x1[k] * mW2[k * 256 + t];
    out[g * 256 + t] = s;
}

// ------------------------- host launch -------------------------
extern "C" void kernel_launch(void* const* d_in, const int* in_sizes, int n_in,
                              void* d_out, int out_size) {
    const float* X     = (const float*)d_in[0];
    const int*   src   = (const int*)d_in[1];
    const int*   dst   = (const int*)d_in[2];
    const int*   gid   = (const int*)d_in[3];
    const float* projW = (const float*)d_in[4];
    const float* projb = (const float*)d_in[5];
    const float* fcW1  = (const float*)d_in[6];
    const float* al1   = (const float*)d_in[7];
    const float* ar1   = (const float*)d_in[8];
    const float* resW1 = (const float*)d_in[9];
    const float* b1    = (const float*)d_in[10];
    const float* fcW2  = (const float*)d_in[11];
    const float* al2   = (const float*)d_in[12];
    const float* ar2   = (const float*)d_in[13];
    const float* b2    = (const float*)d_in[14];
    const float* gW1   = (const float*)d_in[15];
    const float* gb1   = (const float*)d_in[16];
    const float* gW2   = (const float*)d_in[17];
    const float* gb2   = (const float*)d_in[18];
    const float* mW0   = (const float*)d_in[19];
    const float* mb0   = (const float*)d_in[20];
    const float* mW1   = (const float*)d_in[21];
    const float* mb1   = (const float*)d_in[22];
    const float* mW2   = (const float*)d_in[23];
    const float* mb2   = (const float*)d_in[24];
    float* out = (float*)d_out;

    int N = in_sizes[0] / HF;
    int E = in_sizes[1];
    if (N > NMAX) N = NMAX;
    if (E > EMAX) E = EMAX;

    float *p_h, *p_agg, *p_rst, *p_el, *p_er, *p_h2, *p_hg, *p_pool1, *p_pool2, *p_w;
    float *p_wl1, *p_wr1, *p_wl2, *p_wr2;
    int *p_indeg, *p_cursor, *p_rowptr, *p_srcs, *p_pos;
    cudaGetSymbolAddress((void**)&p_h, g_h);
    cudaGetSymbolAddress((void**)&p_agg, g_agg);
    cudaGetSymbolAddress((void**)&p_rst, g_rst);
    cudaGetSymbolAddress((void**)&p_el, g_el);
    cudaGetSymbolAddress((void**)&p_er, g_er);
    cudaGetSymbolAddress((void**)&p_h2, g_h2);
    cudaGetSymbolAddress((void**)&p_hg, g_hg);
    cudaGetSymbolAddress((void**)&p_pool1, g_pool1);
    cudaGetSymbolAddress((void**)&p_pool2, g_pool2);
    cudaGetSymbolAddress((void**)&p_w, g_w);
    cudaGetSymbolAddress((void**)&p_indeg, g_indeg);
    cudaGetSymbolAddress((void**)&p_cursor, g_cursor);
    cudaGetSymbolAddress((void**)&p_rowptr, g_rowptr);
    cudaGetSymbolAddress((void**)&p_srcs, g_srcs);
    cudaGetSymbolAddress((void**)&p_pos, g_pos);
    cudaGetSymbolAddress((void**)&p_wl1, g_wl1);
    cudaGetSymbolAddress((void**)&p_wr1, g_wr1);
    cudaGetSymbolAddress((void**)&p_wl2, g_wl2);
    cudaGetSymbolAddress((void**)&p_wr2, g_wr2);

    int rowTiles = (N + 127) / 128;
    int eBlocks = (E + 255) / 256;
    int nfBlocks = (N * 64 + 255) / 256;
    int nWarpBlocks = (N + 7) / 8;

    // init + CSR
    k_init<<<(N + 255) / 256, 256>>>(p_indeg, p_cursor, p_hg, p_pool1, p_pool2, N);
    k_hist<<<eBlocks, 256>>>(dst, p_indeg, E);
    k_scan<<<1, 1024>>>(p_indeg, p_rowptr, N);
    k_prep_all<<<3, 256>>>(fcW1, al1, ar1, fcW2, al2, ar2, p_wl1, p_wr1, p_wl2, p_wr2);

    // projection (+ hg pool fused)
    k_gemm_proj<<<rowTiles, 128>>>(X, projW, projb, gid, p_h, p_hg, N);

    // --- GAT layer 1 ---
    k_attn<8><<<nWarpBlocks, 256>>>(p_h, p_wl1, p_wr1, p_el, p_er, N);
    k_edge1_h8<<<eBlocks, 256>>>(src, dst, p_el, p_er, p_rowptr, p_cursor,
                                 p_srcs, p_pos, p_w, E);
    k_agg_h8<<<nWarpBlocks, 256>>>(p_srcs, p_h, p_w, p_rowptr, p_agg, N);
    k_gemm_cat1<<<dim3(rowTiles, 8), 128>>>(p_agg, p_h, fcW1, resW1, b1, p_rst, N);
    k_mean8<<<nfBlocks, 256>>>(p_rst, gid, p_h2, p_pool1, N);
    k_hg_update<<<GNUM, 64>>>(p_pool1, gW1, gb1, p_hg);

    // --- GAT layer 2 ---
    k_attn<1><<<nWarpBlocks, 256>>>(p_h2, p_wl2, p_wr2, p_el, p_er, N);
    k_edge2_h1<<<eBlocks, 256>>>(src, dst, p_el, p_er, p_pos, p_w, E);
    k_agg_h1<<<nWarpBlocks, 256>>>(p_srcs, p_h2, p_w, p_rowptr, p_agg, N);
    k_gemm_epi2<<<rowTiles, 128>>>(p_agg, fcW2, p_h2, b2, gid, p_pool2, N);
    k_hg_update<<<GNUM, 64>>>(p_pool2, gW2, gb2, p_hg);

    // --- MLP head ---
    k_mlp<<<GNUM, 256>>>(p_hg, mW0, mb0, mW1, mb1, mW2, mb2, out);
}

// round 5
// speedup vs baseline: 1.2984x; 1.2984x over previous
#include <cuda_runtime.h>
#include <cuda_bf16.h>
#include <math_constants.h>

#define NMAX 30000
#define EMAX 480000
#define GNUM 64
#define HF 64
#define HEADS 8
#define MLPD 256

// ------------------------- device scratch -------------------------
__device__ float g_h   [NMAX * HF];
__device__ float g_agg [NMAX * HEADS * HF];
__device__ float g_rst [NMAX * HEADS * HF];
__device__ float g_el  [NMAX * HEADS];
__device__ float g_er  [NMAX * HEADS];
__device__ float g_h2  [NMAX * HF];
__device__ float g_w   [EMAX * HEADS];
__device__ int   g_indeg [NMAX];
__device__ int   g_cursor[NMAX];
__device__ int   g_rowptr[NMAX + 1];
__device__ int   g_srcs  [EMAX];
__device__ int   g_pos   [EMAX];
__device__ float g_hg   [GNUM * HF];
__device__ float g_pool1[GNUM * HF];
__device__ float g_pool2[GNUM * HF];
__device__ float g_wl1[HEADS * HF], g_wr1[HEADS * HF];
__device__ float g_wl2[HF],        g_wr2[HF];

// ------------------------- tf32 helpers -------------------------
__device__ __forceinline__ unsigned cvt_tf32(float x) {
    unsigned r;
    asm("cvt.rna.tf32.f32 %0, %1;" : "=r"(r) : "f"(x));
    return r;
}
#define MMA_TF32(d, a, b)                                                     \
    asm("mma.sync.aligned.m16n8k8.row.col.f32.tf32.tf32.f32 "                 \
        "{%0,%1,%2,%3}, {%4,%5,%6,%7}, {%8,%9}, {%0,%1,%2,%3};"               \
        : "+f"(d[0]), "+f"(d[1]), "+f"(d[2]), "+f"(d[3])                      \
        : "r"(a[0]), "r"(a[1]), "r"(a[2]), "r"(a[3]), "r"(b[0]), "r"(b[1]))

// ------------------------- init / CSR -------------------------
__global__ void k_init(int* indeg, int* cursor, float* hg, float* pool1, float* pool2, int N) {
    int i = blockIdx.x * blockDim.x + threadIdx.x;
    if (i < N) { indeg[i] = 0; cursor[i] = 0; }
    if (i < GNUM * HF) { hg[i] = 0.f; pool1[i] = 0.f; pool2[i] = 0.f; }
}

__global__ void k_hist(const int* __restrict__ dst, int* __restrict__ indeg, int E) {
    int e = blockIdx.x * blockDim.x + threadIdx.x;
    if (e < E) atomicAdd(&indeg[dst[e]], 1);
}

__global__ void k_scan(const int* __restrict__ indeg, int* __restrict__ rowptr, int n) {
    __shared__ int warpsum[32];
    __shared__ int s_total;
    int t = threadIdx.x, lane = t & 31, w = t >> 5;
    int carry = 0;
    for (int base = 0; base < n; base += 1024) {
        int idx = base + t;
        int v = (idx < n) ? indeg[idx] : 0;
        int x = v;
#pragma unroll
        for (int o = 1; o < 32; o <<= 1) {
            int y = __shfl_up_sync(~0u, x, o);
            if (lane >= o) x += y;
        }
        if (lane == 31) warpsum[w] = x;
        __syncthreads();
        if (w == 0) {
            int y = warpsum[lane];
#pragma unroll
            for (int o = 1; o < 32; o <<= 1) {
                int z = __shfl_up_sync(~0u, y, o);
                if (lane >= o) y += z;
            }
            warpsum[lane] = y;
            if (lane == 31) s_total = y;
        }
        __syncthreads();
        int off = carry + (w ? warpsum[w - 1] : 0);
        if (idx < n) rowptr[idx] = off + x - v;
        carry += s_total;
        __syncthreads();
    }
    if (t == 0) rowptr[n] = carry;
}

// ------------------------- attention prep (coalesced, warp per output) -------------------------
__global__ void k_prep(const float* __restrict__ fcW1, const float* __restrict__ al1,
                       const float* __restrict__ ar1, const float* __restrict__ fcW2,
                       const float* __restrict__ al2, const float* __restrict__ ar2,
                       float* __restrict__ wl1, float* __restrict__ wr1,
                       float* __restrict__ wl2, float* __restrict__ wr2) {
    int gw = (blockIdx.x * blockDim.x + threadIdx.x) >> 5;
    int lane = threadIdx.x & 31;
    if (gw < 512) {
        int h = gw >> 6, i = gw & 63;
        float2 v = *(const float2*)&fcW1[i * 512 + h * 64 + lane * 2];
        float2 a = *(const float2*)&al1[h * 64 + lane * 2];
        float2 r = *(const float2*)&ar1[h * 64 + lane * 2];
        float sl = v.x * a.x + v.y * a.y;
        float sr = v.x * r.x + v.y * r.y;
#pragma unroll
        for (int o = 16; o; o >>= 1) {
            sl += __shfl_xor_sync(~0u, sl, o);
            sr += __shfl_xor_sync(~0u, sr, o);
        }
        if (lane == 0) { wl1[gw] = sl; wr1[gw] = sr; }
    } else if (gw < 576) {
        int i = gw - 512;
        float2 v = *(const float2*)&fcW2[i * 64 + lane * 2];
        float2 a = *(const float2*)&al2[lane * 2];
        float2 r = *(const float2*)&ar2[lane * 2];
        float sl = v.x * a.x + v.y * a.y;
        float sr = v.x * r.x + v.y * r.y;
#pragma unroll
        for (int o = 16; o; o >>= 1) {
            sl += __shfl_xor_sync(~0u, sl, o);
            sr += __shfl_xor_sync(~0u, sr, o);
        }
        if (lane == 0) { wl2[i] = sl; wr2[i] = sr; }
    }
}

// ------------------------- attention coefficients -------------------------
template <int H>
__global__ void k_attn(const float* __restrict__ hfeat, const float* __restrict__ wl,
                       const float* __restrict__ wr, float* __restrict__ el,
                       float* __restrict__ er, int N) {
    __shared__ float swl[H * 64], swr[H * 64];
    int t = threadIdx.x;
    for (int i = t; i < H * 64; i += blockDim.x) { swl[i] = wl[i]; swr[i] = wr[i]; }
    __syncthreads();
    int lane = t & 31;
    int node = blockIdx.x * (blockDim.x >> 5) + (t >> 5);
    if (node >= N) return;
    float2 f = *(const float2*)&hfeat[(size_t)node * 64 + lane * 2];
#pragma unroll
    for (int h = 0; h < H; h++) {
        float sl = f.x * swl[h * 64 + lane * 2] + f.y * swl[h * 64 + lane * 2 + 1];
        float sr = f.x * swr[h * 64 + lane * 2] + f.y * swr[h * 64 + lane * 2 + 1];
#pragma unroll
        for (int o = 16; o; o >>= 1) {
            sl += __shfl_xor_sync(~0u, sl, o);
            sr += __shfl_xor_sync(~0u, sr, o);
        }
        if (lane == 0) { el[node * H + h] = sl; er[node * H + h] = sr; }
    }
}

// ------------------------- edge kernels -------------------------
__global__ void k_edge1_h8(const int* __restrict__ src, const int* __restrict__ dst,
                           const float* __restrict__ el, const float* __restrict__ er,
                           const int* __restrict__ rowptr, int* __restrict__ cursor,
                           int* __restrict__ srcs, int* __restrict__ pos_out,
                           float* __restrict__ w, int E) {
    int e = blockIdx.x * blockDim.x + threadIdx.x;
    if (e >= E) return;
    int s = src[e], d = dst[e];
    int pos = rowptr[d] + atomicAdd(&cursor[d], 1);
    pos_out[e] = pos;
    srcs[pos] = s;
    float4 el0 = *(const float4*)&el[s * 8];
    float4 el1 = *(const float4*)&el[s * 8 + 4];
    float4 er0 = *(const float4*)&er[d * 8];
    float4 er1 = *(const float4*)&er[d * 8 + 4];
    float x[8] = {el0.x + er0.x, el0.y + er0.y, el0.z + er0.z, el0.w + er0.w,
                  el1.x + er1.x, el1.y + er1.y, el1.z + er1.z, el1.w + er1.w};
    float4 w0, w1;
#pragma unroll
    for (int h = 0; h < 8; h++) {
        float v = x[h] > 0.f ? x[h] : 0.2f * x[h];
        float ex = __expf(v);
        if (h < 4) ((float*)&w0)[h] = ex; else ((float*)&w1)[h - 4] = ex;
    }
    *(float4*)&w[(size_t)pos * 8] = w0;
    *(float4*)&w[(size_t)pos * 8 + 4] = w1;
}

__global__ void k_edge2_h1(const int* __restrict__ src, const int* __restrict__ dst,
                           const float* __restrict__ el, const float* __restrict__ er,
                           const int* __restrict__ pos_in, float* __restrict__ w, int E) {
    int e = blockIdx.x * blockDim.x + threadIdx.x;
    if (e >= E) return;
    float x = el[src[e]] + er[dst[e]];
    x = x > 0.f ? x : 0.2f * x;
    w[pos_in[e]] = __expf(x);
}

// ------------------------- aggregation -------------------------
__global__ void k_agg_h8(const int* __restrict__ srcs, const float* __restrict__ hfeat,
                         const float* __restrict__ w, const int* __restrict__ rowptr,
                         float* __restrict__ agg, int N) {
    int node = blockIdx.x * 8 + (threadIdx.x >> 5);
    int lane = threadIdx.x & 31;
    if (node >= N) return;
    int rs = rowptr[node], deg = rowptr[node + 1] - rs;
    float ax[8], ay[8], den[8];
#pragma unroll
    for (int h = 0; h < 8; h++) { ax[h] = 0.f; ay[h] = 0.f; den[h] = 0.f; }
    for (int k = 0; k < deg; k++) {
        int s = srcs[rs + k];
        float2 hv = *(const float2*)&hfeat[(size_t)s * 64 + lane * 2];
        float4 w0 = *(const float4*)&w[(size_t)(rs + k) * 8];
        float4 w1 = *(const float4*)&w[(size_t)(rs + k) * 8 + 4];
        const float* ww = (const float*)&w0;
#pragma unroll
        for (int h = 0; h < 4; h++) {
            ax[h] += ww[h] * hv.x; ay[h] += ww[h] * hv.y; den[h] += ww[h];
        }
        const float* ww2 = (const float*)&w1;
#pragma unroll
        for (int h = 0; h < 4; h++) {
            ax[4 + h] += ww2[h] * hv.x; ay[4 + h] += ww2[h] * hv.y; den[4 + h] += ww2[h];
        }
    }
#pragma unroll
    for (int h = 0; h < 8; h++) {
        float inv = (deg > 0) ? 1.f / den[h] : 0.f;
        *(float2*)&agg[(size_t)node * 512 + h * 64 + lane * 2] =
            make_float2(ax[h] * inv, ay[h] * inv);
    }
}

__global__ void k_agg_h1(const int* __restrict__ srcs, const float* __restrict__ hfeat,
                         const float* __restrict__ w, const int* __restrict__ rowptr,
                         float* __restrict__ agg, int N) {
    int node = blockIdx.x * 8 + (threadIdx.x >> 5);
    int lane = threadIdx.x & 31;
    if (node >= N) return;
    int rs = rowptr[node], deg = rowptr[node + 1] - rs;
    float ax = 0.f, ay = 0.f, den = 0.f;
    for (int k = 0; k < deg; k++) {
        int s = srcs[rs + k];
        float ww = w[rs + k];
        float2 hv = *(const float2*)&hfeat[(size_t)s * 64 + lane * 2];
        ax += ww * hv.x; ay += ww * hv.y; den += ww;
    }
    float inv = (deg > 0) ? 1.f / den : 0.f;
    *(float2*)&agg[(size_t)node * 64 + lane * 2] = make_float2(ax * inv, ay * inv);
}

// ------------------------- proj GEMM (round-3 core) + fused hg pool -------------------------
__global__ void k_gemm_proj(const float* __restrict__ X, const float* __restrict__ W,
                            const float* __restrict__ bias, const int* __restrict__ gid,
                            float* __restrict__ h, float* __restrict__ hg, int M) {
    __shared__ float As[64][65];
    __shared__ float Ws[64][64];
    int m0 = blockIdx.x * 64;
    int t = threadIdx.x;
    for (int i = t; i < 1024; i += 256) {
        int r = i >> 4, c = (i & 15) << 2;
        int row = m0 + r;
        float4 v = (row < M) ? *(const float4*)&X[(size_t)row * 64 + c]
                             : make_float4(0.f, 0.f, 0.f, 0.f);
        As[r][c] = v.x; As[r][c + 1] = v.y; As[r][c + 2] = v.z; As[r][c + 3] = v.w;
    }
    for (int i = t; i < 1024; i += 256) {
        int k = i >> 4, c = (i & 15) << 2;
        *(float4*)&Ws[k][c] = *(const float4*)&W[(size_t)k * 64 + c];
    }
    __syncthreads();
    int tx = t & 15, ty = t >> 4;
    float acc[4][4] = {};
#pragma unroll 16
    for (int k = 0; k < 64; k++) {
        float a0 = As[ty * 4 + 0][k];
        float a1 = As[ty * 4 + 1][k];
        float a2 = As[ty * 4 + 2][k];
        float a3 = As[ty * 4 + 3][k];
        float4 b = *(float4*)&Ws[k][tx * 4];
        acc[0][0] += a0 * b.x; acc[0][1] += a0 * b.y; acc[0][2] += a0 * b.z; acc[0][3] += a0 * b.w;
        acc[1][0] += a1 * b.x; acc[1][1] += a1 * b.y; acc[1][2] += a1 * b.z; acc[1][3] += a1 * b.w;
        acc[2][0] += a2 * b.x; acc[2][1] += a2 * b.y; acc[2][2] += a2 * b.z; acc[2][3] += a2 * b.w;
        acc[3][0] += a3 * b.x; acc[3][1] += a3 * b.y; acc[3][2] += a3 * b.z; acc[3][3] += a3 * b.w;
    }
    float4 bv = *(const float4*)&bias[tx * 4];
#pragma unroll
    for (int i = 0; i < 4; i++) {
        int row = m0 + ty * 4 + i;
        if (row < M) {
            float4 o;
            o.x = acc[i][0] + bv.x; o.y = acc[i][1] + bv.y;
            o.z = acc[i][2] + bv.z; o.w = acc[i][3] + bv.w;
            *(float4*)&h[(size_t)row * 64 + tx * 4] = o;
            int g = gid[row];
            atomicAdd(&hg[g * 64 + tx * 4 + 0], o.x);
            atomicAdd(&hg[g * 64 + tx * 4 + 1], o.y);
            atomicAdd(&hg[g * 64 + tx * 4 + 2], o.z);
            atomicAdd(&hg[g * 64 + tx * 4 + 3], o.w);
        }
    }
}

// ------------------------- cat1: tf32 MMA + bias + ELU + LN -> rst -------------------------
union SmemU {
    struct { float As[128][36]; float Ws[32][72]; } in;
    float Cs[128][68];
};

__global__ __launch_bounds__(256) void k_cat1_tf32(
    const float* __restrict__ agg, const float* __restrict__ hfeat,
    const float* __restrict__ fcW1, const float* __restrict__ resW1,
    const float* __restrict__ bias, float* __restrict__ rst, int M) {
    __shared__ SmemU sm;
    int t = threadIdx.x, lane = t & 31, wid = t >> 5;
    int wr = wid >> 1, wc = wid & 1;      // warp tile: rows wr*32, cols wc*32
    int m0 = blockIdx.x * 128, hb = blockIdx.y;
    float acc[2][4][4];
#pragma unroll
    for (int mi = 0; mi < 2; mi++)
#pragma unroll
        for (int ni = 0; ni < 4; ni++)
#pragma unroll
            for (int r = 0; r < 4; r++) acc[mi][ni][r] = 0.f;

#pragma unroll
    for (int c = 0; c < 4; c++) {   // K = 128 in chunks of 32 ([agg_h | h])
        const float* Ap = (c < 2) ? agg : hfeat;
        int lda = (c < 2) ? 512 : 64;
        int aoff = ((c < 2) ? hb * 64 : 0) + (c & 1) * 32;
        const float* Wp = (c < 2) ? fcW1 : resW1;
        int k0 = (c & 1) * 32;
#pragma unroll
        for (int j = 0; j < 4; j++) {
            int idx = t + 256 * j;
            int r = idx >> 3, c4 = idx & 7;
            int row = m0 + r;
            float4 v = (row < M) ? *(const float4*)&Ap[(size_t)row * lda + aoff + c4 * 4]
                                 : make_float4(0.f, 0.f, 0.f, 0.f);
            sm.in.As[r][c4 * 4 + 0] = v.x; sm.in.As[r][c4 * 4 + 1] = v.y;
            sm.in.As[r][c4 * 4 + 2] = v.z; sm.in.As[r][c4 * 4 + 3] = v.w;
        }
#pragma unroll
        for (int j = 0; j < 2; j++) {
            int idx = t + 256 * j;
            int k = idx >> 4, c4 = idx & 15;
            float4 v = *(const float4*)&Wp[(size_t)(k0 + k) * 512 + hb * 64 + c4 * 4];
            sm.in.Ws[k][c4 * 4 + 0] = v.x; sm.in.Ws[k][c4 * 4 + 1] = v.y;
            sm.in.Ws[k][c4 * 4 + 2] = v.z; sm.in.Ws[k][c4 * 4 + 3] = v.w;
        }
        __syncthreads();
#pragma unroll
        for (int kc = 0; kc < 32; kc += 8) {
            unsigned a[2][4], b[4][2];
#pragma unroll
            for (int mi = 0; mi < 2; mi++) {
                int r0 = wr * 32 + mi * 16 + (lane >> 2);
                int cc = kc + (lane & 3);
                a[mi][0] = cvt_tf32(sm.in.As[r0][cc]);
                a[mi][1] = cvt_tf32(sm.in.As[r0 + 8][cc]);
                a[mi][2] = cvt_tf32(sm.in.As[r0][cc + 4]);
                a[mi][3] = cvt_tf32(sm.in.As[r0 + 8][cc + 4]);
            }
#pragma unroll
            for (int ni = 0; ni < 4; ni++) {
                int n0 = wc * 32 + ni * 8 + (lane >> 2);
                b[ni][0] = cvt_tf32(sm.in.Ws[kc + (lane & 3)][n0]);
                b[ni][1] = cvt_tf32(sm.in.Ws[kc + (lane & 3) + 4][n0]);
            }
#pragma unroll
            for (int mi = 0; mi < 2; mi++)
#pragma unroll
                for (int ni = 0; ni < 4; ni++) MMA_TF32(acc[mi][ni], a[mi], b[ni]);
        }
        __syncthreads();
    }
    // epilogue: bias + ELU into Cs (union-safe: all As/Ws reads done at last sync)
#pragma unroll
    for (int mi = 0; mi < 2; mi++)
#pragma unroll
        for (int ni = 0; ni < 4; ni++) {
            int r0 = wr * 32 + mi * 16 + (lane >> 2);
            int c0 = wc * 32 + ni * 8 + (lane & 3) * 2;
            float b0v = bias[hb * 64 + c0], b1v = bias[hb * 64 + c0 + 1];
            float v;
            v = acc[mi][ni][0] + b0v; v = v > 0.f ? v : expm1f(v); sm.Cs[r0][c0] = v;
            v = acc[mi][ni][1] + b1v; v = v > 0.f ? v : expm1f(v); sm.Cs[r0][c0 + 1] = v;
            v = acc[mi][ni][2] + b0v; v = v > 0.f ? v : expm1f(v); sm.Cs[r0 + 8][c0] = v;
            v = acc[mi][ni][3] + b1v; v = v > 0.f ? v : expm1f(v); sm.Cs[r0 + 8][c0 + 1] = v;
        }
    __syncthreads();
    // LayerNorm: 2 threads per row (halves of 32 cols), partner via shfl xor 1
    int row = t >> 1, half = t & 1;
    float vals[32];
    float s = 0.f, q = 0.f;
#pragma unroll
    for (int j = 0; j < 32; j++) {
        float v = sm.Cs[row][half * 32 + j];
        vals[j] = v; s += v; q += v * v;
    }
    s += __shfl_xor_sync(~0u, s, 1);
    q += __shfl_xor_sync(~0u, q, 1);
    float mu = s * (1.f / 64.f);
    float sc = rsqrtf(q * (1.f / 64.f) - mu * mu + 1e-5f);
    int grow = m0 + row;
    if (grow < M) {
#pragma unroll
        for (int j = 0; j < 32; j += 4) {
            float4 o = make_float4((vals[j] - mu) * sc, (vals[j + 1] - mu) * sc,
                                   (vals[j + 2] - mu) * sc, (vals[j + 3] - mu) * sc);
            *(float4*)&rst[(size_t)grow * 512 + hb * 64 + half * 32 + j] = o;
        }
    }
}

// ------------------------- head mean + pool1 -------------------------
__global__ void k_mean8(const float* __restrict__ rst, const int* __restrict__ gid,
                        float* __restrict__ h2, float* __restrict__ pool1, int N) {
    int i = blockIdx.x * blockDim.x + threadIdx.x;
    if (i >= N * 64) return;
    int n = i >> 6, c = i & 63;
    float s = 0.f;
#pragma unroll
    for (int h = 0; h < 8; h++) s += rst[(size_t)n * 512 + h * 64 + c];
    s *= 0.125f;
    h2[i] = s;
    atomicAdd(&pool1[gid[n] * 64 + c], s);
}

// -------- layer2 GEMM (round-3 core) + identity residual + bias + ELU + LN + pool2 --------
__global__ void k_gemm_epi2(const float* __restrict__ agg2, const float* __restrict__ fcW2,
                            const float* __restrict__ h2, const float* __restrict__ bias,
                            const int* __restrict__ gid, float* __restrict__ pool2, int M) {
    __shared__ float As[64][65];
    __shared__ float Ws[64][64];
    __shared__ float rsum[64][17];
    __shared__ float rsq [64][17];
    __shared__ float stats[64][2];
    int m0 = blockIdx.x * 64;
    int t = threadIdx.x;
    for (int i = t; i < 1024; i += 256) {
        int r = i >> 4, c = (i & 15) << 2;
        int row = m0 + r;
        float4 v = (row < M) ? *(const float4*)&agg2[(size_t)row * 64 + c]
                             : make_float4(0.f, 0.f, 0.f, 0.f);
        As[r][c] = v.x; As[r][c + 1] = v.y; As[r][c + 2] = v.z; As[r][c + 3] = v.w;
    }
    for (int i = t; i < 1024; i += 256) {
        int k = i >> 4, c = (i & 15) << 2;
        *(float4*)&Ws[k][c] = *(const float4*)&fcW2[(size_t)k * 64 + c];
    }
    __syncthreads();
    int tx = t & 15, ty = t >> 4;
    float acc[4][4] = {};
#pragma unroll 16
    for (int k = 0; k < 64; k++) {
        float a0 = As[ty * 4 + 0][k];
        float a1 = As[ty * 4 + 1][k];
        float a2 = As[ty * 4 + 2][k];
        float a3 = As[ty * 4 + 3][k];
        float4 b = *(float4*)&Ws[k][tx * 4];
        acc[0][0] += a0 * b.x; acc[0][1] += a0 * b.y; acc[0][2] += a0 * b.z; acc[0][3] += a0 * b.w;
        acc[1][0] += a1 * b.x; acc[1][1] += a1 * b.y; acc[1][2] += a1 * b.z; acc[1][3] += a1 * b.w;
        acc[2][0] += a2 * b.x; acc[2][1] += a2 * b.y; acc[2][2] += a2 * b.z; acc[2][3] += a2 * b.w;
        acc[3][0] += a3 * b.x; acc[3][1] += a3 * b.y; acc[3][2] += a3 * b.z; acc[3][3] += a3 * b.w;
    }
    float4 bv = *(const float4*)&bias[tx * 4];
#pragma unroll
    for (int i = 0; i < 4; i++) {
        int row = m0 + ty * 4 + i;
        float4 hv = (row < M) ? *(const float4*)&h2[(size_t)row * 64 + tx * 4]
                              : make_float4(0.f, 0.f, 0.f, 0.f);
        float v0 = acc[i][0] + hv.x + bv.x;
        float v1 = acc[i][1] + hv.y + bv.y;
        float v2 = acc[i][2] + hv.z + bv.z;
        float v3 = acc[i][3] + hv.w + bv.w;
        v0 = v0 > 0.f ? v0 : expm1f(v0);
        v1 = v1 > 0.f ? v1 : expm1f(v1);
        v2 = v2 > 0.f ? v2 : expm1f(v2);
        v3 = v3 > 0.f ? v3 : expm1f(v3);
        acc[i][0] = v0; acc[i][1] = v1; acc[i][2] = v2; acc[i][3] = v3;
        rsum[ty * 4 + i][tx] = v0 + v1 + v2 + v3;
        rsq [ty * 4 + i][tx] = v0 * v0 + v1 * v1 + v2 * v2 + v3 * v3;
    }
    __syncthreads();
    if (t < 64) {
        float s = 0.f, q = 0.f;
#pragma unroll
        for (int j = 0; j < 16; j++) { s += rsum[t][j]; q += rsq[t][j]; }
        float mu = s * (1.f / 64.f);
        float var = q * (1.f / 64.f) - mu * mu;
        stats[t][0] = mu;
        stats[t][1] = rsqrtf(var + 1e-5f);
    }
    __syncthreads();
#pragma unroll
    for (int i = 0; i < 4; i++) {
        int row = m0 + ty * 4 + i;
        if (row < M) {
            float mu = stats[ty * 4 + i][0], sc = stats[ty * 4 + i][1];
            int g = gid[row];
            atomicAdd(&pool2[g * 64 + tx * 4 + 0], (acc[i][0] - mu) * sc);
            atomicAdd(&pool2[g * 64 + tx * 4 + 1], (acc[i][1] - mu) * sc);
            atomicAdd(&pool2[g * 64 + tx * 4 + 2], (acc[i][2] - mu) * sc);
            atomicAdd(&pool2[g * 64 + tx * 4 + 3], (acc[i][3] - mu) * sc);
        }
    }
}

// ------------------------- graph head -------------------------
__global__ void k_hg_update(const float* __restrict__ p, const float* __restrict__ W,
                            const float* __restrict__ b, float* __restrict__ hg) {
    int g = blockIdx.x, f = threadIdx.x;
    __shared__ float pr[64];
    pr[f] = p[g * 64 + f];
    __syncthreads();
    float s = b[f];
#pragma unroll 16
    for (int k = 0; k < 64; k++) s += pr[k] * W[k * 64 + f];
    s = s > 0.f ? s : 0.01f * s;
    hg[g * 64 + f] += s;
}

__global__ void k_mlp(const float* __restrict__ hg, const float* __restrict__ mW0,
                      const float* __restrict__ mb0, const float* __restrict__ mW1,
                      const float* __restrict__ mb1, const float* __restrict__ mW2,
                      const float* __restrict__ mb2, float* __restrict__ out) {
    int g = blockIdx.x;
    int t = threadIdx.x;
    __shared__ float x0[64], x1[256];
    if (t < 64) x0[t] = hg[g * 64 + t];
    __syncthreads();
    float s = mb0[t];
#pragma unroll 16
    for (int k = 0; k < 64; k++) s += x0[k] * mW0[k * 256 + t];
    x1[t] = fmaxf(s, 0.f);
    __syncthreads();
    s = mb1[t];
#pragma unroll 16
    for (int k = 0; k < 256; k++) s += x1[k] * mW1[k * 256 + t];
    float y = fmaxf(s, 0.f);
    __syncthreads();
    x1[t] = y;
    __syncthreads();
    s = mb2[t];
#pragma unroll 16
    for (int k = 0; k < 256; k++) s += x1[k] * mW2[k * 256 + t];
    out[g * 256 + t] = s;
}

// ------------------------- host launch -------------------------
extern "C" void kernel_launch(void* const* d_in, const int* in_sizes, int n_in,
                              void* d_out, int out_size) {
    const float* X     = (const float*)d_in[0];
    const int*   src   = (const int*)d_in[1];
    const int*   dst   = (const int*)d_in[2];
    const int*   gid   = (const int*)d_in[3];
    const float* projW = (const float*)d_in[4];
    const float* projb = (const float*)d_in[5];
    const float* fcW1  = (const float*)d_in[6];
    const float* al1   = (const float*)d_in[7];
    const float* ar1   = (const float*)d_in[8];
    const float* resW1 = (const float*)d_in[9];
    const float* b1    = (const float*)d_in[10];
    const float* fcW2  = (const float*)d_in[11];
    const float* al2   = (const float*)d_in[12];
    const float* ar2   = (const float*)d_in[13];
    const float* b2    = (const float*)d_in[14];
    const float* gW1   = (const float*)d_in[15];
    const float* gb1   = (const float*)d_in[16];
    const float* gW2   = (const float*)d_in[17];
    const float* gb2   = (const float*)d_in[18];
    const float* mW0   = (const float*)d_in[19];
    const float* mb0   = (const float*)d_in[20];
    const float* mW1   = (const float*)d_in[21];
    const float* mb1   = (const float*)d_in[22];
    const float* mW2   = (const float*)d_in[23];
    const float* mb2   = (const float*)d_in[24];
    float* out = (float*)d_out;

    int N = in_sizes[0] / HF;
    int E = in_sizes[1];
    if (N > NMAX) N = NMAX;
    if (E > EMAX) E = EMAX;

    float *p_h, *p_agg, *p_rst, *p_el, *p_er, *p_h2, *p_hg, *p_pool1, *p_pool2, *p_w;
    float *p_wl1, *p_wr1, *p_wl2, *p_wr2;
    int *p_indeg, *p_cursor, *p_rowptr, *p_srcs, *p_pos;
    cudaGetSymbolAddress((void**)&p_h, g_h);
    cudaGetSymbolAddress((void**)&p_agg, g_agg);
    cudaGetSymbolAddress((void**)&p_rst, g_rst);
    cudaGetSymbolAddress((void**)&p_el, g_el);
    cudaGetSymbolAddress((void**)&p_er, g_er);
    cudaGetSymbolAddress((void**)&p_h2, g_h2);
    cudaGetSymbolAddress((void**)&p_hg, g_hg);
    cudaGetSymbolAddress((void**)&p_pool1, g_pool1);
    cudaGetSymbolAddress((void**)&p_pool2, g_pool2);
    cudaGetSymbolAddress((void**)&p_w, g_w);
    cudaGetSymbolAddress((void**)&p_indeg, g_indeg);
    cudaGetSymbolAddress((void**)&p_cursor, g_cursor);
    cudaGetSymbolAddress((void**)&p_rowptr, g_rowptr);
    cudaGetSymbolAddress((void**)&p_srcs, g_srcs);
    cudaGetSymbolAddress((void**)&p_pos, g_pos);
    cudaGetSymbolAddress((void**)&p_wl1, g_wl1);
    cudaGetSymbolAddress((void**)&p_wr1, g_wr1);
    cudaGetSymbolAddress((void**)&p_wl2, g_wl2);
    cudaGetSymbolAddress((void**)&p_wr2, g_wr2);

    int rowTiles64 = (N + 63) / 64;
    int rowTiles128 = (N + 127) / 128;
    int eBlocks = (E + 255) / 256;
    int nfBlocks = (N * 64 + 255) / 256;
    int nWarpBlocks = (N + 7) / 8;

    // init + CSR
    k_init<<<(N + 255) / 256, 256>>>(p_indeg, p_cursor, p_hg, p_pool1, p_pool2, N);
    k_hist<<<eBlocks, 256>>>(dst, p_indeg, E);
    k_scan<<<1, 1024>>>(p_indeg, p_rowptr, N);
    k_prep<<<72, 256>>>(fcW1, al1, ar1, fcW2, al2, ar2, p_wl1, p_wr1, p_wl2, p_wr2);

    // projection (+ hg pool fused)
    k_gemm_proj<<<rowTiles64, 256>>>(X, projW, projb, gid, p_h, p_hg, N);

    // --- GAT layer 1 ---
    k_attn<8><<<nWarpBlocks, 256>>>(p_h, p_wl1, p_wr1, p_el, p_er, N);
    k_edge1_h8<<<eBlocks, 256>>>(src, dst, p_el, p_er, p_rowptr, p_cursor,
                                 p_srcs, p_pos, p_w, E);
    k_agg_h8<<<nWarpBlocks, 256>>>(p_srcs, p_h, p_w, p_rowptr, p_agg, N);
    k_cat1_tf32<<<dim3(rowTiles128, 8), 256>>>(p_agg, p_h, fcW1, resW1, b1, p_rst, N);
    k_mean8<<<nfBlocks, 256>>>(p_rst, gid, p_h2, p_pool1, N);
    k_hg_update<<<GNUM, 64>>>(p_pool1, gW1, gb1, p_hg);

    // --- GAT layer 2 ---
    k_attn<1><<<nWarpBlocks, 256>>>(p_h2, p_wl2, p_wr2, p_el, p_er, N);
    k_edge2_h1<<<eBlocks, 256>>>(src, dst, p_el, p_er, p_pos, p_w, E);
    k_agg_h1<<<nWarpBlocks, 256>>>(p_srcs, p_h2, p_w, p_rowptr, p_agg, N);
    k_gemm_epi2<<<rowTiles64, 256>>>(p_agg, fcW2, p_h2, b2, gid, p_pool2, N);
    k_hg_update<<<GNUM, 64>>>(p_pool2, gW2, gb2, p_hg);

    // --- MLP head ---
    k_mlp<<<GNUM, 256>>>(p_hg, mW0, mb0, mW1, mb1, mW2, mb2, out);
}